// round 13
// baseline (speedup 1.0000x reference)
#include <cuda_runtime.h>
#include <cuda_bf16.h>
#include <cstdint>

#define QSZ 128
#define BATCH 4096
typedef unsigned long long ull;

// ---------------- f32x2 packed-FMA helpers (conv1) -------------------------------
__device__ __forceinline__ ull pack2(float lo, float hi) {
    ull r; asm("mov.b64 %0, {%1, %2};" : "=l"(r) : "f"(lo), "f"(hi)); return r;
}
__device__ __forceinline__ void fma2(ull& d, ull a, ull b) {
    asm("fma.rn.f32x2 %0, %1, %2, %0;" : "+l"(d) : "l"(a), "l"(b));
}
__device__ __forceinline__ void unpack2(ull v, float& lo, float& hi) {
    asm("mov.b64 {%0, %1}, %2;" : "=f"(lo), "=f"(hi) : "l"(v));
}

// ---------------- mma.sync / ldmatrix / cp.async helpers (sm_80+ generic) --------
__device__ __forceinline__ uint32_t smem_u32(const void* p) {
    uint32_t a;
    asm("{ .reg .u64 t; cvta.to.shared.u64 t, %1; cvt.u32.u64 %0, t; }" : "=r"(a) : "l"(p));
    return a;
}
__device__ __forceinline__ void ldsm4(uint32_t* r, uint32_t addr) {
    asm volatile("ldmatrix.sync.aligned.m8n8.x4.shared.b16 {%0,%1,%2,%3}, [%4];"
                 : "=r"(r[0]), "=r"(r[1]), "=r"(r[2]), "=r"(r[3]) : "r"(addr));
}
__device__ __forceinline__ void mma_bf16(float* d, const uint32_t* a, const uint32_t* b) {
    asm volatile("mma.sync.aligned.m16n8k16.row.col.f32.bf16.bf16.f32 "
                 "{%0,%1,%2,%3}, {%4,%5,%6,%7}, {%8,%9}, {%0,%1,%2,%3};"
                 : "+f"(d[0]), "+f"(d[1]), "+f"(d[2]), "+f"(d[3])
                 : "r"(a[0]), "r"(a[1]), "r"(a[2]), "r"(a[3]), "r"(b[0]), "r"(b[1]));
}
__device__ __forceinline__ void cp16(uint32_t dst, const void* src) {
    asm volatile("cp.async.cg.shared.global [%0], [%1], 16;" :: "r"(dst), "l"(src) : "memory");
}
#define CP_COMMIT() asm volatile("cp.async.commit_group;" ::: "memory")
#define CP_WAITN(n) asm volatile("cp.async.wait_group %0;" :: "n"(n) : "memory")

__device__ __forceinline__ uint32_t laneA_off(int l) {
    return (uint32_t)(((l & 7) + (((l >> 3) & 1) << 3)) * 80 + ((l >> 4) << 4));
}
__device__ __forceinline__ uint32_t laneB_off(int l) {
    return (uint32_t)((((l & 7) + ((l >> 4) << 3)) * 80) + (((l >> 3) & 1) << 4));
}
__device__ __forceinline__ uint32_t laneA_off_c2(int l) {
    return (uint32_t)(((((l >> 3) & 1) * 12 + (l & 7)) * 80) + ((l >> 4) << 4));
}

// ---------------- scratch (static device globals) --------------------------------
__device__ __align__(16) __nv_bfloat16 g_w2bh[25 * 64 * 40];
__device__ __align__(16) __nv_bfloat16 g_w2bl[25 * 64 * 40];
__device__ __align__(16) __nv_bfloat16 g_W3h[512 * 1024];
__device__ __align__(16) __nv_bfloat16 g_W3l[512 * 1024];
__device__ __align__(16) __nv_bfloat16 g_h1th[BATCH * 144 * 40];
__device__ __align__(16) __nv_bfloat16 g_h1tl[BATCH * 144 * 40];
__device__ __align__(16) __nv_bfloat16 g_h2h[BATCH * 1024];
__device__ __align__(16) __nv_bfloat16 g_h2l[BATCH * 1024];
__device__ __align__(16) float g_h3[BATCH * 512];

// ---------------- fused conv1 (first BATCH blocks) + weight build (trailing) -----
#define BUILD_BLOCKS 1274            // 64000 + 262144 pairs = 326144 threads

__global__ __launch_bounds__(256) void conv1_build(
    const float* __restrict__ x,  const float* __restrict__ b1,
    const int* __restrict__ hi1,  const float* __restrict__ s1, const float* __restrict__ w1,
    const int* __restrict__ hi2,  const float* __restrict__ s2, const float* __restrict__ w2,
    const int* __restrict__ hi3,  const float* __restrict__ s3, const float* __restrict__ w3)
{
    __shared__ ull xs2[784];        // image pre-duplicated as (v,v) pairs -> LDS.64
    __shared__ float ws[800];
    int tid = threadIdx.x;

    if ((int)blockIdx.x >= BATCH) {
        int idx0 = ((int)blockIdx.x - BATCH) * 256 + tid;
        if (idx0 < 64000) {
            int j = idx0;
            int m = j / 2560, r = j % 2560;
            int co = r / 40, ci = r % 40;
            float v = 0.f;
            if (ci < 32) {
                int s = ci * 25 + m;
                v = w2[co * QSZ + hi2[s]] * s2[s];
            }
            __nv_bfloat16 h = __float2bfloat16(v);
            g_w2bh[j] = h;
            g_w2bl[j] = __float2bfloat16(v - __bfloat162float(h));
        } else {
            int j2 = (idx0 - 64000) * 2;
            int n = j2 >> 10, kp = j2 & 1023;
            int pos = kp >> 6, co = kp & 63;
            int k0 = co * 16 + pos, k1 = (co + 1) * 16 + pos;
            float v0 = w3[n * QSZ + hi3[k0]] * s3[k0];
            float v1 = w3[n * QSZ + hi3[k1]] * s3[k1];
            __nv_bfloat16 h0 = __float2bfloat16(v0);
            __nv_bfloat16 h1 = __float2bfloat16(v1);
            *(__nv_bfloat162*)&g_W3h[j2] = __halves2bfloat162(h0, h1);
            *(__nv_bfloat162*)&g_W3l[j2] = __halves2bfloat162(
                __float2bfloat16(v0 - __bfloat162float(h0)),
                __float2bfloat16(v1 - __bfloat162float(h1)));
        }
        return;
    }

    int b = blockIdx.x;
    for (int t = tid; t < 784; t += 256) {
        float v = x[b * 784 + t];
        xs2[t] = pack2(v, v);
    }
    for (int t = tid; t < 800; t += 256) {
        int m = t >> 5, o = t & 31;
        ws[t] = w1[o * QSZ + hi1[m]] * s1[m];
    }
    __syncthreads();

    int cp = tid & 15, slot = tid >> 4;
    int co = cp * 2;
    ull w[25];
#pragma unroll
    for (int m = 0; m < 25; m++) w[m] = *(const ull*)&ws[m * 32 + co];
    float bias0 = b1[co], bias1 = b1[co + 1];

#pragma unroll 1
    for (int it = 0; it < 9; it++) {
        int pos = slot + it * 16;
        int py = pos / 12, px = pos % 12;
        int r0 = 2 * py, c0 = 2 * px;
        ull acc[4] = {0ull, 0ull, 0ull, 0ull};
#pragma unroll
        for (int rr = 0; rr < 6; rr++) {
            ull prow[6];
#pragma unroll
            for (int cc = 0; cc < 6; cc++)
                prow[cc] = xs2[(r0 + rr) * 28 + c0 + cc];     // LDS.64, broadcast
#pragma unroll
            for (int dy = 0; dy < 2; dy++) {
                int ky = rr - dy;
                if (ky >= 0 && ky < 5) {
#pragma unroll
                    for (int dx = 0; dx < 2; dx++)
#pragma unroll
                        for (int kx = 0; kx < 5; kx++)
                            fma2(acc[dy * 2 + dx], prow[dx + kx], w[ky * 5 + kx]);
                }
            }
        }
        float lo[4], hi[4];
#pragma unroll
        for (int i = 0; i < 4; i++) unpack2(acc[i], lo[i], hi[i]);
        float m0 = fmaxf(fmaxf(lo[0], lo[1]), fmaxf(lo[2], lo[3])) + bias0;
        float m1 = fmaxf(fmaxf(hi[0], hi[1]), fmaxf(hi[2], hi[3])) + bias1;
        float v0 = m0 > 0.f ? m0 : 0.f;
        float v1 = m1 > 0.f ? m1 : 0.f;
        __nv_bfloat16 h0 = __float2bfloat16(v0);
        __nv_bfloat16 h1 = __float2bfloat16(v1);
        __nv_bfloat16 l0 = __float2bfloat16(v0 - __bfloat162float(h0));
        __nv_bfloat16 l1 = __float2bfloat16(v1 - __bfloat162float(h1));
        int i0 = b * 5760 + pos * 40 + co;
        *(__nv_bfloat162*)&g_h1th[i0] = __halves2bfloat162(h0, h1);
        *(__nv_bfloat162*)&g_h1tl[i0] = __halves2bfloat162(l0, l1);
    }
}

// ---------------- conv2: 4 images/CTA, 25 shifted K=32 HMMA GEMMs ----------------
#define C2_AIMG 11520
#define C2_ALO  46080
#define C2_B0   92160
#define C2_BSL  5120
#define C2_SMEM (C2_B0 + 4 * C2_BSL)

__global__ __launch_bounds__(256, 2) void conv2_mma(const float* __restrict__ b2)
{
    extern __shared__ char sm[];
    const uint32_t sbase = smem_u32(sm);
    const int tid = threadIdx.x, wid = tid >> 5, l = tid & 31;
    const int b0 = blockIdx.x * 4;
    const int wm = wid >> 1, wn = wid & 1;

    {
        const uint4* srcH = (const uint4*)g_h1th + (size_t)b0 * 720;
        const uint4* srcL = (const uint4*)g_h1tl + (size_t)b0 * 720;
        for (int idx = tid; idx < 2880; idx += 256) {
            cp16(sbase + idx * 16, srcH + idx);
            cp16(sbase + C2_ALO + idx * 16, srcL + idx);
        }
        for (int idx = tid; idx < 320; idx += 256) {
            cp16(sbase + C2_B0 + idx * 16, (const uint4*)g_w2bh + idx);
            cp16(sbase + C2_B0 + C2_BSL + idx * 16, (const uint4*)g_w2bl + idx);
        }
    }
    CP_COMMIT(); CP_WAITN(0);
    __syncthreads();

    float acc[4][4][4];
#pragma unroll
    for (int t = 0; t < 4; t++)
#pragma unroll
        for (int g = 0; g < 4; g++)
#pragma unroll
            for (int i = 0; i < 4; i++) acc[t][g][i] = 0.f;

    const uint32_t aBaseH = sbase + wm * C2_AIMG + laneA_off_c2(l);
    const uint32_t bBase0 = sbase + C2_B0 + wn * 2560 + laneB_off(l);

#pragma unroll 1
    for (int m = 0; m < 25; m++) {
        int buf = m & 1;
        if (m < 24) {
            int mn = m + 1;
            uint32_t bdst = sbase + C2_B0 + (mn & 1) * (2 * C2_BSL);
            for (int idx = tid; idx < 320; idx += 256) {
                cp16(bdst + idx * 16, (const uint4*)g_w2bh + mn * 320 + idx);
                cp16(bdst + C2_BSL + idx * 16, (const uint4*)g_w2bl + mn * 320 + idx);
            }
            CP_COMMIT();
        }
        int ky = m / 5, kx = m % 5;
        uint32_t aH = aBaseH + (uint32_t)(ky * 12 + kx) * 80;
        uint32_t bH = bBase0 + (uint32_t)buf * (2 * C2_BSL);
#pragma unroll
        for (int kh = 0; kh < 2; kh++) {
            uint32_t A_h[4][4], A_l[4][4];
#pragma unroll
            for (int t = 0; t < 4; t++) {
                ldsm4(A_h[t], aH + t * 1920 + kh * 32);
                ldsm4(A_l[t], aH + C2_ALO + t * 1920 + kh * 32);
            }
            uint32_t B_h[8], B_l[8];
#pragma unroll
            for (int p = 0; p < 2; p++) {
                ldsm4(&B_h[p * 4], bH + p * 1280 + kh * 32);
                ldsm4(&B_l[p * 4], bH + C2_BSL + p * 1280 + kh * 32);
            }
#pragma unroll
            for (int t = 0; t < 4; t++)
#pragma unroll
                for (int g = 0; g < 4; g++) {
                    mma_bf16(acc[t][g], A_h[t], &B_h[g * 2]);
                    mma_bf16(acc[t][g], A_h[t], &B_l[g * 2]);
                    mma_bf16(acc[t][g], A_l[t], &B_h[g * 2]);
                }
        }
        if (m < 24) CP_WAITN(0);
        __syncthreads();
    }

    int b = b0 + wm;
    int r = l >> 2, c = l & 3;
#pragma unroll
    for (int t = 0; t < 4; t++)
#pragma unroll
        for (int g = 0; g < 4; g++) {
            float v0 = fmaxf(acc[t][g][0], acc[t][g][2]);
            float v1 = fmaxf(acc[t][g][1], acc[t][g][3]);
            float o0 = __shfl_xor_sync(0xffffffffu, v0, 4);
            float o1 = __shfl_xor_sync(0xffffffffu, v1, 4);
            v0 = fmaxf(v0, o0);
            v1 = fmaxf(v1, o1);
            if ((r & 1) == 0) {
                int px = r >> 1;
                int co = wn * 32 + g * 8 + 2 * c;
                float a0 = v0 + b2[co];
                float a1 = v1 + b2[co + 1];
                a0 = a0 > 0.f ? a0 : 0.f;
                a1 = a1 > 0.f ? a1 : 0.f;
                __nv_bfloat16 h0 = __float2bfloat16(a0);
                __nv_bfloat16 h1 = __float2bfloat16(a1);
                __nv_bfloat16 l0 = __float2bfloat16(a0 - __bfloat162float(h0));
                __nv_bfloat16 l1 = __float2bfloat16(a1 - __bfloat162float(h1));
                int idx = b * 1024 + (t * 4 + px) * 64 + co;
                *(__nv_bfloat162*)&g_h2h[idx] = __halves2bfloat162(h0, h1);
                *(__nv_bfloat162*)&g_h2l[idx] = __halves2bfloat162(l0, l1);
            }
        }
}

// ---------------- FC1 HMMA: CTA 64x128, 3-stage cp.async pipeline ----------------
#define F1_AT  5120
#define F1_BT  10240
#define F1_STG 30720
#define F1_SMEM (3 * F1_STG)

__global__ __launch_bounds__(256, 2) void fc1_mma(const float* __restrict__ b3)
{
    extern __shared__ char sm[];
    const uint32_t sbase = smem_u32(sm);
    const int tid = threadIdx.x, wid = tid >> 5, l = tid & 31;
    const int rowBase = blockIdx.y * 64, colBase = blockIdx.x * 128;
    const int wm = wid >> 2, wn = wid & 3;

    auto stage = [&](int ch, int buf) {
        int k0 = ch * 32;
        uint32_t base = sbase + (uint32_t)buf * F1_STG;
#pragma unroll
        for (int i = 0; i < 6; i++) {
            int idx = tid + i * 256;
            const uint4* src; uint32_t dst;
            if (idx < 512) {
                int arr = idx >> 8, rq = idx & 255;
                int r = rq >> 2, q = rq & 3;
                const __nv_bfloat16* s = (arr ? g_h2l : g_h2h) + (size_t)(rowBase + r) * 1024 + k0;
                src = (const uint4*)s + q;
                dst = base + arr * F1_AT + r * 80 + q * 16;
            } else {
                int j = idx - 512;
                int arr = j >> 9, rq = j & 511;
                int r = rq >> 2, q = rq & 3;
                const __nv_bfloat16* s = (arr ? g_W3l : g_W3h) + (size_t)(colBase + r) * 1024 + k0;
                src = (const uint4*)s + q;
                dst = base + 2 * F1_AT + arr * F1_BT + r * 80 + q * 16;
            }
            cp16(dst, src);
        }
    };

    stage(0, 0); CP_COMMIT();
    stage(1, 1); CP_COMMIT();

    float acc[2][4][4];
#pragma unroll
    for (int t = 0; t < 2; t++)
#pragma unroll
        for (int g = 0; g < 4; g++)
#pragma unroll
            for (int i = 0; i < 4; i++) acc[t][g][i] = 0.f;

    const uint32_t aOff = (uint32_t)(wm * 32) * 80 + laneA_off(l);
    const uint32_t bOff = (uint32_t)(wn * 32) * 80 + laneB_off(l);

#pragma unroll 1
    for (int ch = 0; ch < 32; ch++) {
        if (ch < 31) CP_WAITN(1); else CP_WAITN(0);
        __syncthreads();
        if (ch + 2 < 32) { stage(ch + 2, (ch + 2) % 3); CP_COMMIT(); }
        uint32_t base = sbase + (uint32_t)(ch % 3) * F1_STG;
        uint32_t aH = base + aOff;
        uint32_t bH = base + 2 * F1_AT + bOff;
#pragma unroll
        for (int kh = 0; kh < 2; kh++) {
            uint32_t A_h[2][4], A_l[2][4];
#pragma unroll
            for (int t = 0; t < 2; t++) {
                ldsm4(A_h[t], aH + t * 1280 + kh * 32);
                ldsm4(A_l[t], aH + F1_AT + t * 1280 + kh * 32);
            }
            uint32_t B_h[8], B_l[8];
#pragma unroll
            for (int p = 0; p < 2; p++) {
                ldsm4(&B_h[p * 4], bH + p * 1280 + kh * 32);
                ldsm4(&B_l[p * 4], bH + F1_BT + p * 1280 + kh * 32);
            }
#pragma unroll
            for (int t = 0; t < 2; t++)
#pragma unroll
                for (int g = 0; g < 4; g++) {
                    mma_bf16(acc[t][g], A_h[t], &B_h[g * 2]);
                    mma_bf16(acc[t][g], A_h[t], &B_l[g * 2]);
                    mma_bf16(acc[t][g], A_l[t], &B_h[g * 2]);
                }
        }
        __syncthreads();
    }

    int r = l >> 2, c = l & 3;
#pragma unroll
    for (int t = 0; t < 2; t++) {
        int row0 = rowBase + wm * 32 + 16 * t + r;
#pragma unroll
        for (int g = 0; g < 4; g++) {
            int col = colBase + wn * 32 + g * 8 + 2 * c;
            float bb0 = b3[col], bb1 = b3[col + 1];
            float u0 = acc[t][g][0] + bb0, u1 = acc[t][g][1] + bb1;
            float u2 = acc[t][g][2] + bb0, u3 = acc[t][g][3] + bb1;
            float2 p0 = make_float2(u0 > 0.f ? u0 : 0.f, u1 > 0.f ? u1 : 0.f);
            float2 p1 = make_float2(u2 > 0.f ? u2 : 0.f, u3 > 0.f ? u3 : 0.f);
            *(float2*)&g_h3[(size_t)row0 * 512 + col]       = p0;
            *(float2*)&g_h3[(size_t)(row0 + 8) * 512 + col] = p1;
        }
    }
}

// ---------------- FC2 + log_softmax (float4, 8 rows/block) ------------------------
__global__ __launch_bounds__(256) void fc2_kernel(const float* __restrict__ fw,
                                                  const float* __restrict__ fb,
                                                  float* __restrict__ out)
{
    int warp = threadIdx.x >> 5, lane = threadIdx.x & 31;
    int b = blockIdx.x * 8 + warp;
    const float4* h4 = (const float4*)(g_h3 + (size_t)b * 512);
    float4 hv[4];
#pragma unroll
    for (int q = 0; q < 4; q++) hv[q] = h4[lane + q * 32];

    float acc[10];
#pragma unroll
    for (int o = 0; o < 10; o++) {
        const float4* w4 = (const float4*)(fw + o * 512);
        float a = 0.f;
#pragma unroll
        for (int q = 0; q < 4; q++) {
            float4 w = w4[lane + q * 32];
            a = fmaf(hv[q].x, w.x, a);
            a = fmaf(hv[q].y, w.y, a);
            a = fmaf(hv[q].z, w.z, a);
            a = fmaf(hv[q].w, w.w, a);
        }
        acc[o] = a;
    }
#pragma unroll
    for (int o = 0; o < 10; o++) {
        acc[o] += __shfl_xor_sync(0xffffffffu, acc[o], 16);
        acc[o] += __shfl_xor_sync(0xffffffffu, acc[o], 8);
        acc[o] += __shfl_xor_sync(0xffffffffu, acc[o], 4);
        acc[o] += __shfl_xor_sync(0xffffffffu, acc[o], 2);
        acc[o] += __shfl_xor_sync(0xffffffffu, acc[o], 1);
        acc[o] += fb[o];
    }
    if (lane == 0) {
        float m = acc[0];
#pragma unroll
        for (int o = 1; o < 10; o++) m = fmaxf(m, acc[o]);
        float s = 0.f;
#pragma unroll
        for (int o = 0; o < 10; o++) s += expf(acc[o] - m);
        float lse = m + logf(s);
#pragma unroll
        for (int o = 0; o < 10; o++) out[b * 10 + o] = acc[o] - lse;
    }
}

// ---------------- launch -----------------------------------------------------------
extern "C" void kernel_launch(void* const* d_in, const int* in_sizes, int n_in,
                              void* d_out, int out_size)
{
    const float* x  = (const float*)d_in[0];
    const int*  hi1 = (const int*)d_in[1];
    const int*  hi2 = (const int*)d_in[2];
    const int*  hi3 = (const int*)d_in[3];
    const float* s1 = (const float*)d_in[4];
    const float* s2 = (const float*)d_in[5];
    const float* s3 = (const float*)d_in[6];
    const float* w1 = (const float*)d_in[7];
    const float* b1 = (const float*)d_in[8];
    const float* w2 = (const float*)d_in[9];
    const float* b2 = (const float*)d_in[10];
    const float* w3 = (const float*)d_in[11];
    const float* b3 = (const float*)d_in[12];
    const float* fw = (const float*)d_in[13];
    const float* fb = (const float*)d_in[14];
    float* out = (float*)d_out;

    static int attr_done = 0;
    if (!attr_done) {
        cudaFuncSetAttribute(conv2_mma, cudaFuncAttributeMaxDynamicSharedMemorySize, C2_SMEM);
        cudaFuncSetAttribute(fc1_mma,  cudaFuncAttributeMaxDynamicSharedMemorySize, F1_SMEM);
        attr_done = 1;
    }

    conv1_build<<<BATCH + BUILD_BLOCKS, 256>>>(x, b1, hi1, s1, w1, hi2, s2, w2, hi3, s3, w3);
    conv2_mma<<<BATCH / 4, 256, C2_SMEM>>>(b2);
    fc1_mma<<<dim3(4, 64), 256, F1_SMEM>>>(b3);
    fc2_kernel<<<BATCH / 8, 256>>>(fw, fb, out);
}

// round 14
// speedup vs baseline: 1.0280x; 1.0280x over previous
#include <cuda_runtime.h>
#include <cuda_bf16.h>
#include <cstdint>

#define QSZ 128
#define BATCH 4096
typedef unsigned long long ull;

// ---------------- f32x2 packed-FMA helpers (conv1) -------------------------------
__device__ __forceinline__ ull pack2(float lo, float hi) {
    ull r; asm("mov.b64 %0, {%1, %2};" : "=l"(r) : "f"(lo), "f"(hi)); return r;
}
__device__ __forceinline__ void fma2(ull& d, ull a, ull b) {
    asm("fma.rn.f32x2 %0, %1, %2, %0;" : "+l"(d) : "l"(a), "l"(b));
}
__device__ __forceinline__ void unpack2(ull v, float& lo, float& hi) {
    asm("mov.b64 {%0, %1}, %2;" : "=f"(lo), "=f"(hi) : "l"(v));
}

// ---------------- mma.sync / ldmatrix / cp.async helpers (sm_80+ generic) --------
__device__ __forceinline__ uint32_t smem_u32(const void* p) {
    uint32_t a;
    asm("{ .reg .u64 t; cvta.to.shared.u64 t, %1; cvt.u32.u64 %0, t; }" : "=r"(a) : "l"(p));
    return a;
}
__device__ __forceinline__ void ldsm4(uint32_t* r, uint32_t addr) {
    asm volatile("ldmatrix.sync.aligned.m8n8.x4.shared.b16 {%0,%1,%2,%3}, [%4];"
                 : "=r"(r[0]), "=r"(r[1]), "=r"(r[2]), "=r"(r[3]) : "r"(addr));
}
__device__ __forceinline__ void mma_bf16(float* d, const uint32_t* a, const uint32_t* b) {
    asm volatile("mma.sync.aligned.m16n8k16.row.col.f32.bf16.bf16.f32 "
                 "{%0,%1,%2,%3}, {%4,%5,%6,%7}, {%8,%9}, {%0,%1,%2,%3};"
                 : "+f"(d[0]), "+f"(d[1]), "+f"(d[2]), "+f"(d[3])
                 : "r"(a[0]), "r"(a[1]), "r"(a[2]), "r"(a[3]), "r"(b[0]), "r"(b[1]));
}
__device__ __forceinline__ void cp16(uint32_t dst, const void* src) {
    asm volatile("cp.async.cg.shared.global [%0], [%1], 16;" :: "r"(dst), "l"(src) : "memory");
}
#define CP_COMMIT() asm volatile("cp.async.commit_group;" ::: "memory")
#define CP_WAITN(n) asm volatile("cp.async.wait_group %0;" :: "n"(n) : "memory")

__device__ __forceinline__ uint32_t laneA_off(int l) {
    return (uint32_t)(((l & 7) + (((l >> 3) & 1) << 3)) * 80 + ((l >> 4) << 4));
}
__device__ __forceinline__ uint32_t laneB_off(int l) {
    return (uint32_t)((((l & 7) + ((l >> 4) << 3)) * 80) + (((l >> 3) & 1) << 4));
}
__device__ __forceinline__ uint32_t laneA_off_c2(int l) {
    return (uint32_t)(((((l >> 3) & 1) * 12 + (l & 7)) * 80) + ((l >> 4) << 4));
}

// ---------------- scratch (static device globals) --------------------------------
__device__ __align__(16) __nv_bfloat16 g_w2bh[25 * 64 * 40];
__device__ __align__(16) __nv_bfloat16 g_w2bl[25 * 64 * 40];
__device__ __align__(16) __nv_bfloat16 g_W3h[512 * 1024];
__device__ __align__(16) __nv_bfloat16 g_W3l[512 * 1024];
__device__ __align__(16) __nv_bfloat16 g_h1th[BATCH * 144 * 32];   // DENSE: 64B rows
__device__ __align__(16) __nv_bfloat16 g_h1tl[BATCH * 144 * 32];
__device__ __align__(16) __nv_bfloat16 g_h2h[BATCH * 1024];
__device__ __align__(16) __nv_bfloat16 g_h2l[BATCH * 1024];
__device__ __align__(16) float g_h3[BATCH * 512];

// ---------------- fused conv1 (first BATCH blocks) + weight build (trailing) -----
#define BUILD_BLOCKS 1274            // 64000 + 262144 pairs = 326144 threads

__global__ __launch_bounds__(256) void conv1_build(
    const float* __restrict__ x,  const float* __restrict__ b1,
    const int* __restrict__ hi1,  const float* __restrict__ s1, const float* __restrict__ w1,
    const int* __restrict__ hi2,  const float* __restrict__ s2, const float* __restrict__ w2,
    const int* __restrict__ hi3,  const float* __restrict__ s3, const float* __restrict__ w3)
{
    __shared__ float xs[784];
    __shared__ float ws[800];
    int tid = threadIdx.x;

    if ((int)blockIdx.x >= BATCH) {
        int idx0 = ((int)blockIdx.x - BATCH) * 256 + tid;
        if (idx0 < 64000) {
            int j = idx0;
            int m = j / 2560, r = j % 2560;
            int co = r / 40, ci = r % 40;
            float v = 0.f;
            if (ci < 32) {
                int s = ci * 25 + m;
                v = w2[co * QSZ + hi2[s]] * s2[s];
            }
            __nv_bfloat16 h = __float2bfloat16(v);
            g_w2bh[j] = h;
            g_w2bl[j] = __float2bfloat16(v - __bfloat162float(h));
        } else {
            int j2 = (idx0 - 64000) * 2;
            int n = j2 >> 10, kp = j2 & 1023;
            int pos = kp >> 6, co = kp & 63;
            int k0 = co * 16 + pos, k1 = (co + 1) * 16 + pos;
            float v0 = w3[n * QSZ + hi3[k0]] * s3[k0];
            float v1 = w3[n * QSZ + hi3[k1]] * s3[k1];
            __nv_bfloat16 h0 = __float2bfloat16(v0);
            __nv_bfloat16 h1 = __float2bfloat16(v1);
            *(__nv_bfloat162*)&g_W3h[j2] = __halves2bfloat162(h0, h1);
            *(__nv_bfloat162*)&g_W3l[j2] = __halves2bfloat162(
                __float2bfloat16(v0 - __bfloat162float(h0)),
                __float2bfloat16(v1 - __bfloat162float(h1)));
        }
        return;
    }

    int b = blockIdx.x;
    for (int t = tid; t < 784; t += 256) xs[t] = x[b * 784 + t];
    for (int t = tid; t < 800; t += 256) {
        int m = t >> 5, o = t & 31;
        ws[t] = w1[o * QSZ + hi1[m]] * s1[m];
    }
    __syncthreads();

    int cp = tid & 15, slot = tid >> 4;
    int co = cp * 2;
    ull w[25];
#pragma unroll
    for (int m = 0; m < 25; m++) w[m] = *(const ull*)&ws[m * 32 + co];
    float bias0 = b1[co], bias1 = b1[co + 1];

#pragma unroll 1
    for (int it = 0; it < 9; it++) {
        int pos = slot + it * 16;
        int py = pos / 12, px = pos % 12;
        int r0 = 2 * py, c0 = 2 * px;
        ull acc[4] = {0ull, 0ull, 0ull, 0ull};
#pragma unroll
        for (int rr = 0; rr < 6; rr++) {
            ull prow[6];
#pragma unroll
            for (int cc = 0; cc < 6; cc++) {
                float v = xs[(r0 + rr) * 28 + c0 + cc];
                prow[cc] = pack2(v, v);
            }
#pragma unroll
            for (int dy = 0; dy < 2; dy++) {
                int ky = rr - dy;
                if (ky >= 0 && ky < 5) {
#pragma unroll
                    for (int dx = 0; dx < 2; dx++)
#pragma unroll
                        for (int kx = 0; kx < 5; kx++)
                            fma2(acc[dy * 2 + dx], prow[dx + kx], w[ky * 5 + kx]);
                }
            }
        }
        float lo[4], hi[4];
#pragma unroll
        for (int i = 0; i < 4; i++) unpack2(acc[i], lo[i], hi[i]);
        float m0 = fmaxf(fmaxf(lo[0], lo[1]), fmaxf(lo[2], lo[3])) + bias0;
        float m1 = fmaxf(fmaxf(hi[0], hi[1]), fmaxf(hi[2], hi[3])) + bias1;
        float v0 = m0 > 0.f ? m0 : 0.f;
        float v1 = m1 > 0.f ? m1 : 0.f;
        __nv_bfloat16 h0 = __float2bfloat16(v0);
        __nv_bfloat16 h1 = __float2bfloat16(v1);
        __nv_bfloat16 l0 = __float2bfloat16(v0 - __bfloat162float(h0));
        __nv_bfloat16 l1 = __float2bfloat16(v1 - __bfloat162float(h1));
        int i0 = b * 4608 + pos * 32 + co;          // dense 64B rows
        *(__nv_bfloat162*)&g_h1th[i0] = __halves2bfloat162(h0, h1);
        *(__nv_bfloat162*)&g_h1tl[i0] = __halves2bfloat162(l0, l1);
    }
}

// ---------------- conv2: 4 images/CTA, 25 shifted K=32 HMMA GEMMs ----------------
#define C2_AIMG 11520
#define C2_ALO  46080
#define C2_B0   92160
#define C2_BSL  5120
#define C2_SMEM (C2_B0 + 4 * C2_BSL)

__global__ __launch_bounds__(256, 2) void conv2_mma(const float* __restrict__ b2)
{
    extern __shared__ char sm[];
    const uint32_t sbase = smem_u32(sm);
    const int tid = threadIdx.x, wid = tid >> 5, l = tid & 31;
    const int b0 = blockIdx.x * 4;
    const int wm = wid >> 1, wn = wid & 1;

    // stage A: dense gmem (576 chunks/img) -> padded smem (80B rows)
    {
        for (int idx = tid; idx < 2304; idx += 256) {
            int img = idx / 576, rq = idx % 576;
            int r = rq >> 2, q = rq & 3;
            uint32_t dst = sbase + (uint32_t)(img * C2_AIMG + r * 80 + q * 16);
            cp16(dst, (const uint4*)g_h1th + (size_t)(b0 + img) * 576 + rq);
            cp16(dst + C2_ALO, (const uint4*)g_h1tl + (size_t)(b0 + img) * 576 + rq);
        }
        for (int idx = tid; idx < 320; idx += 256) {
            cp16(sbase + C2_B0 + idx * 16, (const uint4*)g_w2bh + idx);
            cp16(sbase + C2_B0 + C2_BSL + idx * 16, (const uint4*)g_w2bl + idx);
        }
    }
    CP_COMMIT(); CP_WAITN(0);
    __syncthreads();

    float acc[4][4][4];
#pragma unroll
    for (int t = 0; t < 4; t++)
#pragma unroll
        for (int g = 0; g < 4; g++)
#pragma unroll
            for (int i = 0; i < 4; i++) acc[t][g][i] = 0.f;

    const uint32_t aBaseH = sbase + wm * C2_AIMG + laneA_off_c2(l);
    const uint32_t bBase0 = sbase + C2_B0 + wn * 2560 + laneB_off(l);

#pragma unroll 1
    for (int m = 0; m < 25; m++) {
        int buf = m & 1;
        if (m < 24) {
            int mn = m + 1;
            uint32_t bdst = sbase + C2_B0 + (mn & 1) * (2 * C2_BSL);
            for (int idx = tid; idx < 320; idx += 256) {
                cp16(bdst + idx * 16, (const uint4*)g_w2bh + mn * 320 + idx);
                cp16(bdst + C2_BSL + idx * 16, (const uint4*)g_w2bl + mn * 320 + idx);
            }
            CP_COMMIT();
        }
        int ky = m / 5, kx = m % 5;
        uint32_t aH = aBaseH + (uint32_t)(ky * 12 + kx) * 80;
        uint32_t bH = bBase0 + (uint32_t)buf * (2 * C2_BSL);
#pragma unroll
        for (int kh = 0; kh < 2; kh++) {
            uint32_t A_h[4][4], A_l[4][4];
#pragma unroll
            for (int t = 0; t < 4; t++) {
                ldsm4(A_h[t], aH + t * 1920 + kh * 32);
                ldsm4(A_l[t], aH + C2_ALO + t * 1920 + kh * 32);
            }
            uint32_t B_h[8], B_l[8];
#pragma unroll
            for (int p = 0; p < 2; p++) {
                ldsm4(&B_h[p * 4], bH + p * 1280 + kh * 32);
                ldsm4(&B_l[p * 4], bH + C2_BSL + p * 1280 + kh * 32);
            }
            // three sweeps: 16 independent MMAs per sweep (explicit ILP)
#pragma unroll
            for (int t = 0; t < 4; t++)
#pragma unroll
                for (int g = 0; g < 4; g++)
                    mma_bf16(acc[t][g], A_h[t], &B_h[g * 2]);
#pragma unroll
            for (int t = 0; t < 4; t++)
#pragma unroll
                for (int g = 0; g < 4; g++)
                    mma_bf16(acc[t][g], A_h[t], &B_l[g * 2]);
#pragma unroll
            for (int t = 0; t < 4; t++)
#pragma unroll
                for (int g = 0; g < 4; g++)
                    mma_bf16(acc[t][g], A_l[t], &B_h[g * 2]);
        }
        if (m < 24) CP_WAITN(0);
        __syncthreads();
    }

    int b = b0 + wm;
    int r = l >> 2, c = l & 3;
#pragma unroll
    for (int t = 0; t < 4; t++)
#pragma unroll
        for (int g = 0; g < 4; g++) {
            float v0 = fmaxf(acc[t][g][0], acc[t][g][2]);
            float v1 = fmaxf(acc[t][g][1], acc[t][g][3]);
            float o0 = __shfl_xor_sync(0xffffffffu, v0, 4);
            float o1 = __shfl_xor_sync(0xffffffffu, v1, 4);
            v0 = fmaxf(v0, o0);
            v1 = fmaxf(v1, o1);
            if ((r & 1) == 0) {
                int px = r >> 1;
                int co = wn * 32 + g * 8 + 2 * c;
                float a0 = v0 + b2[co];
                float a1 = v1 + b2[co + 1];
                a0 = a0 > 0.f ? a0 : 0.f;
                a1 = a1 > 0.f ? a1 : 0.f;
                __nv_bfloat16 h0 = __float2bfloat16(a0);
                __nv_bfloat16 h1 = __float2bfloat16(a1);
                __nv_bfloat16 l0 = __float2bfloat16(a0 - __bfloat162float(h0));
                __nv_bfloat16 l1 = __float2bfloat16(a1 - __bfloat162float(h1));
                int idx = b * 1024 + (t * 4 + px) * 64 + co;
                *(__nv_bfloat162*)&g_h2h[idx] = __halves2bfloat162(h0, h1);
                *(__nv_bfloat162*)&g_h2l[idx] = __halves2bfloat162(l0, l1);
            }
        }
}

// ---------------- FC1 HMMA: CTA 64x128, 3-stage cp.async pipeline ----------------
#define F1_AT  5120
#define F1_BT  10240
#define F1_STG 30720
#define F1_SMEM (3 * F1_STG)

__global__ __launch_bounds__(256, 2) void fc1_mma(const float* __restrict__ b3)
{
    extern __shared__ char sm[];
    const uint32_t sbase = smem_u32(sm);
    const int tid = threadIdx.x, wid = tid >> 5, l = tid & 31;
    const int rowBase = blockIdx.y * 64, colBase = blockIdx.x * 128;
    const int wm = wid >> 2, wn = wid & 3;

    auto stage = [&](int ch, int buf) {
        int k0 = ch * 32;
        uint32_t base = sbase + (uint32_t)buf * F1_STG;
#pragma unroll
        for (int i = 0; i < 6; i++) {
            int idx = tid + i * 256;
            const uint4* src; uint32_t dst;
            if (idx < 512) {
                int arr = idx >> 8, rq = idx & 255;
                int r = rq >> 2, q = rq & 3;
                const __nv_bfloat16* s = (arr ? g_h2l : g_h2h) + (size_t)(rowBase + r) * 1024 + k0;
                src = (const uint4*)s + q;
                dst = base + arr * F1_AT + r * 80 + q * 16;
            } else {
                int j = idx - 512;
                int arr = j >> 9, rq = j & 511;
                int r = rq >> 2, q = rq & 3;
                const __nv_bfloat16* s = (arr ? g_W3l : g_W3h) + (size_t)(colBase + r) * 1024 + k0;
                src = (const uint4*)s + q;
                dst = base + 2 * F1_AT + arr * F1_BT + r * 80 + q * 16;
            }
            cp16(dst, src);
        }
    };

    stage(0, 0); CP_COMMIT();
    stage(1, 1); CP_COMMIT();

    float acc[2][4][4];
#pragma unroll
    for (int t = 0; t < 2; t++)
#pragma unroll
        for (int g = 0; g < 4; g++)
#pragma unroll
            for (int i = 0; i < 4; i++) acc[t][g][i] = 0.f;

    const uint32_t aOff = (uint32_t)(wm * 32) * 80 + laneA_off(l);
    const uint32_t bOff = (uint32_t)(wn * 32) * 80 + laneB_off(l);

#pragma unroll 1
    for (int ch = 0; ch < 32; ch++) {
        if (ch < 31) CP_WAITN(1); else CP_WAITN(0);
        __syncthreads();
        if (ch + 2 < 32) { stage(ch + 2, (ch + 2) % 3); CP_COMMIT(); }
        uint32_t base = sbase + (uint32_t)(ch % 3) * F1_STG;
        uint32_t aH = base + aOff;
        uint32_t bH = base + 2 * F1_AT + bOff;
#pragma unroll
        for (int kh = 0; kh < 2; kh++) {
            uint32_t A_h[2][4], A_l[2][4];
#pragma unroll
            for (int t = 0; t < 2; t++) {
                ldsm4(A_h[t], aH + t * 1280 + kh * 32);
                ldsm4(A_l[t], aH + F1_AT + t * 1280 + kh * 32);
            }
            uint32_t B_h[8], B_l[8];
#pragma unroll
            for (int p = 0; p < 2; p++) {
                ldsm4(&B_h[p * 4], bH + p * 1280 + kh * 32);
                ldsm4(&B_l[p * 4], bH + F1_BT + p * 1280 + kh * 32);
            }
            // three sweeps: 8 independent MMAs per sweep
#pragma unroll
            for (int t = 0; t < 2; t++)
#pragma unroll
                for (int g = 0; g < 4; g++)
                    mma_bf16(acc[t][g], A_h[t], &B_h[g * 2]);
#pragma unroll
            for (int t = 0; t < 2; t++)
#pragma unroll
                for (int g = 0; g < 4; g++)
                    mma_bf16(acc[t][g], A_h[t], &B_l[g * 2]);
#pragma unroll
            for (int t = 0; t < 2; t++)
#pragma unroll
                for (int g = 0; g < 4; g++)
                    mma_bf16(acc[t][g], A_l[t], &B_h[g * 2]);
        }
        __syncthreads();
    }

    int r = l >> 2, c = l & 3;
#pragma unroll
    for (int t = 0; t < 2; t++) {
        int row0 = rowBase + wm * 32 + 16 * t + r;
#pragma unroll
        for (int g = 0; g < 4; g++) {
            int col = colBase + wn * 32 + g * 8 + 2 * c;
            float bb0 = b3[col], bb1 = b3[col + 1];
            float u0 = acc[t][g][0] + bb0, u1 = acc[t][g][1] + bb1;
            float u2 = acc[t][g][2] + bb0, u3 = acc[t][g][3] + bb1;
            float2 p0 = make_float2(u0 > 0.f ? u0 : 0.f, u1 > 0.f ? u1 : 0.f);
            float2 p1 = make_float2(u2 > 0.f ? u2 : 0.f, u3 > 0.f ? u3 : 0.f);
            *(float2*)&g_h3[(size_t)row0 * 512 + col]       = p0;
            *(float2*)&g_h3[(size_t)(row0 + 8) * 512 + col] = p1;
        }
    }
}

// ---------------- FC2 + log_softmax (float4, 8 rows/block) ------------------------
__global__ __launch_bounds__(256) void fc2_kernel(const float* __restrict__ fw,
                                                  const float* __restrict__ fb,
                                                  float* __restrict__ out)
{
    int warp = threadIdx.x >> 5, lane = threadIdx.x & 31;
    int b = blockIdx.x * 8 + warp;
    const float4* h4 = (const float4*)(g_h3 + (size_t)b * 512);
    float4 hv[4];
#pragma unroll
    for (int q = 0; q < 4; q++) hv[q] = h4[lane + q * 32];

    float acc[10];
#pragma unroll
    for (int o = 0; o < 10; o++) {
        const float4* w4 = (const float4*)(fw + o * 512);
        float a = 0.f;
#pragma unroll
        for (int q = 0; q < 4; q++) {
            float4 w = w4[lane + q * 32];
            a = fmaf(hv[q].x, w.x, a);
            a = fmaf(hv[q].y, w.y, a);
            a = fmaf(hv[q].z, w.z, a);
            a = fmaf(hv[q].w, w.w, a);
        }
        acc[o] = a;
    }
#pragma unroll
    for (int o = 0; o < 10; o++) {
        acc[o] += __shfl_xor_sync(0xffffffffu, acc[o], 16);
        acc[o] += __shfl_xor_sync(0xffffffffu, acc[o], 8);
        acc[o] += __shfl_xor_sync(0xffffffffu, acc[o], 4);
        acc[o] += __shfl_xor_sync(0xffffffffu, acc[o], 2);
        acc[o] += __shfl_xor_sync(0xffffffffu, acc[o], 1);
        acc[o] += fb[o];
    }
    if (lane == 0) {
        float m = acc[0];
#pragma unroll
        for (int o = 1; o < 10; o++) m = fmaxf(m, acc[o]);
        float s = 0.f;
#pragma unroll
        for (int o = 0; o < 10; o++) s += expf(acc[o] - m);
        float lse = m + logf(s);
#pragma unroll
        for (int o = 0; o < 10; o++) out[b * 10 + o] = acc[o] - lse;
    }
}

// ---------------- launch -----------------------------------------------------------
extern "C" void kernel_launch(void* const* d_in, const int* in_sizes, int n_in,
                              void* d_out, int out_size)
{
    const float* x  = (const float*)d_in[0];
    const int*  hi1 = (const int*)d_in[1];
    const int*  hi2 = (const int*)d_in[2];
    const int*  hi3 = (const int*)d_in[3];
    const float* s1 = (const float*)d_in[4];
    const float* s2 = (const float*)d_in[5];
    const float* s3 = (const float*)d_in[6];
    const float* w1 = (const float*)d_in[7];
    const float* b1 = (const float*)d_in[8];
    const float* w2 = (const float*)d_in[9];
    const float* b2 = (const float*)d_in[10];
    const float* w3 = (const float*)d_in[11];
    const float* b3 = (const float*)d_in[12];
    const float* fw = (const float*)d_in[13];
    const float* fb = (const float*)d_in[14];
    float* out = (float*)d_out;

    static int attr_done = 0;
    if (!attr_done) {
        cudaFuncSetAttribute(conv2_mma, cudaFuncAttributeMaxDynamicSharedMemorySize, C2_SMEM);
        cudaFuncSetAttribute(fc1_mma,  cudaFuncAttributeMaxDynamicSharedMemorySize, F1_SMEM);
        attr_done = 1;
    }

    conv1_build<<<BATCH + BUILD_BLOCKS, 256>>>(x, b1, hi1, s1, w1, hi2, s2, w2, hi3, s3, w3);
    conv2_mma<<<BATCH / 4, 256, C2_SMEM>>>(b2);
    fc1_mma<<<dim3(4, 64), 256, F1_SMEM>>>(b3);
    fc2_kernel<<<BATCH / 8, 256>>>(fw, fb, out);
}